// round 15
// baseline (speedup 1.0000x reference)
#include <cuda_runtime.h>

#define Bn 32
#define Nn 4096
#define Kn 16
#define PTS 128                 // points per block
#define NBLK (Nn / PTS)         // 32 blocks per batch
#define GRIDA (Bn * NBLK)       // 1024 blocks x 256 threads

typedef unsigned long long u64;

// Deterministic scratch (no allocations allowed)
__device__ float g_comb[GRIDA];             // rec + kld partial (pre-weighted)
__device__ float g_col_partial[GRIDA * Kn]; // assign column partials
__device__ unsigned int g_count = 0;

__device__ __forceinline__ float flog2(float x) {
    float y; asm("lg2.approx.f32 %0, %1;" : "=f"(y) : "f"(x)); return y;
}
__device__ __forceinline__ float fexp2(float x) {
    float y; asm("ex2.approx.f32 %0, %1;" : "=f"(y) : "f"(x)); return y;
}
__device__ __forceinline__ u64 pack2(float lo, float hi) {
    u64 d; asm("mov.b64 %0, {%1,%2};" : "=l"(d) : "f"(lo), "f"(hi)); return d;
}
__device__ __forceinline__ void unpack2(u64 d, float &lo, float &hi) {
    asm("mov.b64 {%0,%1}, %2;" : "=f"(lo), "=f"(hi) : "l"(d));
}
__device__ __forceinline__ u64 ffma2(u64 a, u64 b, u64 c) {
    u64 d; asm("fma.rn.f32x2 %0, %1, %2, %3;" : "=l"(d) : "l"(a), "l"(b), "l"(c)); return d;
}
__device__ __forceinline__ u64 fmul2(u64 a, u64 b) {
    u64 d; asm("mul.rn.f32x2 %0, %1, %2;" : "=l"(d) : "l"(a), "l"(b)); return d;
}

// Scalar tail for one (point,k) item: argmax/clip + log-domain superquadric -> d
__device__ __forceinline__ float sq_item(
    float c0, float c1, float c2, float w0, float w1, float w2,
    float q0, float q1, float q2, float s0, float s1, float s2,
    float he0, float he1, float he01)
{
    const float a0 = fabsf(w0), a1 = fabsf(w1), a2 = fabsf(w2);
    const bool g0 = (a0 >= a1) & (a0 >= a2);
    const bool g1 = (!g0) & (a1 >= a2);
    const bool g2 = !(g0 | g1);
    const float p0 = g0 ? copysignf(s0, w0) : fminf(fmaxf(q0, -s0), s0);
    const float p1 = g1 ? copysignf(s1, w1) : fminf(fmaxf(q1, -s1), s1);
    const float p2 = g2 ? copysignf(s2, w2) : fminf(fmaxf(q2, -s2), s2);

    const float p0sq = fmaf(p0, p0, 1e-30f);
    const float p1sq = fmaf(p1, p1, 1e-30f);
    const float p2sq = fmaf(p2, p2, 1e-30f);
    const float r2   = p0sq + p1sq;
    const float rho2 = r2 + p2sq;

    const float Lr = flog2(r2);
    const float Lh = flog2(rho2);
    const float L0 = flog2(p0sq);
    const float L1 = flog2(p1sq);
    const float L2 = flog2(p2sq);

    const float hLh = he0 * Lh;
    const float u   = fmaf(he01, Lr, -hLh);
    const float X = copysignf(s0 * fexp2(fmaf(he1, L0, u)), p0);
    const float Y = copysignf(s1 * fexp2(fmaf(he1, L1, u)), p1);
    const float Z = copysignf(s2 * fexp2(fmaf(he0, L2, -hLh)), p2);

    const float dx = X - c0, dy = Y - c1, dz = Z - c2;
    return fmaf(dx, dx, fmaf(dy, dy, dz * dz));
}

__global__ __launch_bounds__(256, 4) void loss_fused_kernel(
    const float* __restrict__ pc, const float* __restrict__ normals,
    const float* __restrict__ randn, const float* __restrict__ scale,
    const float* __restrict__ shapes, const float* __restrict__ rotate,
    const float* __restrict__ pam, const float* __restrict__ assign,
    const float* __restrict__ exist, const float* __restrict__ mu,
    const float* __restrict__ logvar, const float* __restrict__ trans,
    float* __restrict__ out)
{
    // scalar params, stride 20: [0-8]=R, [9-11]=s, [12]=he0,[13]=he1,[14]=he01,[15-17]=ncc
    __shared__ __align__(16) float sP[Kn * 20];
    // packed params: pair j covers (k=j, k=j+8); 20 float2 per pair, same index map
    __shared__ __align__(16) float2 sPP[8 * 20];
    __shared__ float sM[Kn * 3];
    __shared__ __align__(16) float sA[PTS * 20]; // assign rows, stride-20
    __shared__ float scol2[256];
    __shared__ float srec[8];
    __shared__ float skld[4];
    __shared__ float sfin[512];
    __shared__ bool  isLast;

    const int blk   = blockIdx.x;
    const int b     = blk >> 5;          // batch
    const int t     = threadIdx.x;
    const int lane  = t & 31;
    const int warp  = t >> 5;
    const int nl    = t & (PTS - 1);     // local point id
    const int khalf = t >> 7;            // 0: pairs 0..3 (k 0-3 & 8-11); 1: pairs 4..7
    const int n     = (blk & 31) * PTS + nl;

    // Stage per-(b,k) parameters
    if (t < 144) sP[(t / 9) * 20 + (t % 9)]      = rotate[b * 144 + t];
    if (t < 48)  sP[(t / 3) * 20 + 9 + (t % 3)]  = scale [b * 48  + t];
    if (t < 32)  sP[(t / 2) * 20 + 12 + (t & 1)] = 0.5f * shapes[b * 32 + t];
    if (t < 48)  sM[t]                           = pam   [b * 48  + t];

    // Assign weights: lo quad (k = khalf*4..) and hi quad (k+8); regs + stage to sA
    float akLo[4], akHi[4];
    {
        const float4* av = reinterpret_cast<const float4*>(assign)
                         + ((size_t)b * Nn + n) * 4;
        const float4 alo = av[khalf];       // k = khalf*4 .. khalf*4+3
        const float4 ahi = av[khalf + 2];   // k = khalf*4+8 .. khalf*4+11
        akLo[0]=alo.x; akLo[1]=alo.y; akLo[2]=alo.z; akLo[3]=alo.w;
        akHi[0]=ahi.x; akHi[1]=ahi.y; akHi[2]=ahi.z; akHi[3]=ahi.w;
        float4* dst = reinterpret_cast<float4*>(sA + nl * 20);
        dst[khalf]     = alo;
        dst[khalf + 2] = ahi;
    }

    // KLD slice for this block (4 elements)
    if (t < 4) {
        const int id = blk * 4 + t;
        const float lv = logvar[id], m = mu[id];
        skld[t] = 1.f + lv - m * m - expf(lv);
    }
    __syncthreads();

    // ncc = -(R^T mean); he01 = he0 - he1
    if (t < 48) {
        const int k = t / 3, i = t % 3;
        const float* R = sP + k * 20;
        const float* m = sM + k * 3;
        sP[k * 20 + 15 + i] = -(R[i] * m[0] + R[3 + i] * m[1] + R[6 + i] * m[2]);
    } else if (t >= 64 && t < 80) {
        const int k = t - 64;
        sP[k * 20 + 14] = sP[k * 20 + 12] - sP[k * 20 + 13];
    }
    __syncthreads();

    // Build packed params: sPP[j][i] = { sP[j][i], sP[j+8][i] }
    if (t < 144) {
        const int j = t / 18, i = t % 18;
        sPP[j * 20 + i] = make_float2(sP[j * 20 + i], sP[(j + 8) * 20 + i]);
    }
    __syncthreads();

    // Point state (raw normals: argmax scale-invariant; psi uses raw normal offset)
    const size_t pi = ((size_t)b * Nn + n) * 3;
    const float px = pc[pi], py = pc[pi + 1], pz = pc[pi + 2];
    const float nx = normals[pi], ny = normals[pi + 1], nz = normals[pi + 2];
    const float rn0 = randn[b * Nn + n] * 0.01f;

    // Broadcast point into packed lanes (once)
    const u64 PX = pack2(px, px), PY = pack2(py, py), PZ = pack2(pz, pz);
    const u64 NX = pack2(nx, nx), NY = pack2(ny, ny), NZ = pack2(nz, nz);
    const u64 RN = pack2(rn0, rn0);

    float recLo = 0.f, recHi = 0.f;

    #pragma unroll
    for (int jp = 0; jp < 4; jp++) {
        const int j = khalf * 4 + jp;
        const ulonglong2* Pv = reinterpret_cast<const ulonglong2*>(sPP + j * 20);
        const ulonglong2 v0 = Pv[0];  // R0, R1
        const ulonglong2 v1 = Pv[1];  // R2, R3
        const ulonglong2 v2 = Pv[2];  // R4, R5
        const ulonglong2 v3 = Pv[3];  // R6, R7
        const ulonglong2 v4 = Pv[4];  // R8, s0
        const ulonglong2 v5 = Pv[5];  // s1, s2
        const ulonglong2 v6 = Pv[6];  // he0, he1
        const ulonglong2 v7 = Pv[7];  // he01, ncc0
        const ulonglong2 v8 = Pv[8];  // ncc1, ncc2

        // packed matvecs over (k, k+8)
        const u64 c0 = ffma2(v0.x, PX, ffma2(v1.y, PY, ffma2(v3.x, PZ, v7.y)));
        const u64 c1 = ffma2(v0.y, PX, ffma2(v2.x, PY, ffma2(v3.y, PZ, v8.x)));
        const u64 c2 = ffma2(v1.x, PX, ffma2(v2.y, PY, ffma2(v4.x, PZ, v8.y)));
        const u64 w0 = ffma2(v0.x, NX, ffma2(v1.y, NY, fmul2(v3.x, NZ)));
        const u64 w1 = ffma2(v0.y, NX, ffma2(v2.x, NY, fmul2(v3.y, NZ)));
        const u64 w2 = ffma2(v1.x, NX, ffma2(v2.y, NY, fmul2(v4.x, NZ)));
        const u64 q0 = ffma2(RN, w0, c0);
        const u64 q1 = ffma2(RN, w1, c1);
        const u64 q2 = ffma2(RN, w2, c2);

        // unpack (register-pair aliasing) and run scalar tails per lane
        float c0a,c0b,c1a,c1b,c2a,c2b, w0a,w0b,w1a,w1b,w2a,w2b, q0a,q0b,q1a,q1b,q2a,q2b;
        unpack2(c0,c0a,c0b); unpack2(c1,c1a,c1b); unpack2(c2,c2a,c2b);
        unpack2(w0,w0a,w0b); unpack2(w1,w1a,w1b); unpack2(w2,w2a,w2b);
        unpack2(q0,q0a,q0b); unpack2(q1,q1a,q1b); unpack2(q2,q2a,q2b);
        float s0a,s0b,s1a,s1b,s2a,s2b, he0a,he0b,he1a,he1b,he01a,he01b;
        unpack2(v4.y,s0a,s0b); unpack2(v5.x,s1a,s1b); unpack2(v5.y,s2a,s2b);
        unpack2(v6.x,he0a,he0b); unpack2(v6.y,he1a,he1b); unpack2(v7.x,he01a,he01b);

        const float dLo = sq_item(c0a,c1a,c2a, w0a,w1a,w2a, q0a,q1a,q2a,
                                  s0a,s1a,s2a, he0a,he1a,he01a);
        const float dHi = sq_item(c0b,c1b,c2b, w0b,w1b,w2b, q0b,q1b,q2b,
                                  s0b,s1b,s2b, he0b,he1b,he01b);
        recLo = fmaf(dLo, akLo[jp], recLo);
        recHi = fmaf(dHi, akHi[jp], recHi);
    }

    float rec = recLo + recHi;

    // --- block reductions (deterministic) ---
    #pragma unroll
    for (int off = 16; off; off >>= 1)
        rec += __shfl_down_sync(0xffffffffu, rec, off);
    if (lane == 0) srec[warp] = rec;

    // assign column sums from sA: thread t sums 8 rows of column (t&15)
    {
        const int kcol = t & 15, chunk = t >> 4;   // 16 chunks x 8 rows = 128 rows
        float csum = 0.f;
        #pragma unroll
        for (int i = 0; i < 8; i++)
            csum += sA[(chunk * 8 + i) * 20 + kcol];
        scol2[t] = csum;
    }
    __syncthreads();

    if (t == 0) {
        float s = 0.f;
        #pragma unroll
        for (int w = 0; w < 8; w++) s += srec[w];
        float kp = skld[0] + skld[1] + skld[2] + skld[3];
        g_comb[blk] = s * (1.0f / (32.f * 4096.f)) + kp * (-0.5f * 0.001f / 32.f);
    }
    if (t < Kn) {
        float s = 0.f;
        #pragma unroll
        for (int c = 0; c < 16; c++) s += scol2[t + c * 16];
        g_col_partial[blk * Kn + t] = s;
    }

    // --- last-block-done: fused final reduction ---
    __threadfence();
    __syncthreads();
    if (t == 0) {
        unsigned int v = atomicAdd(&g_count, 1u);
        isLast = (v == GRIDA - 1);
    }
    __syncthreads();
    if (!isLast) return;
    __threadfence();

    float acc = g_comb[t] + g_comb[t + 256] + g_comb[t + 512] + g_comb[t + 768];

    // cs for (b,k) pairs p = t and p = t+256
    float cs0 = 0.f, cs1 = 0.f;
    {
        const int b0 = t >> 4, b1 = (t + 256) >> 4, kc = t & 15;
        #pragma unroll
        for (int nb2 = 0; nb2 < 32; nb2++) {
            cs0 += g_col_partial[((b0 * 32 + nb2) << 4) + kc];
            cs1 += g_col_partial[((b1 * 32 + nb2) << 4) + kc];
        }
        sfin[t]       = sqrtf(cs0 * (1.f / 4096.f) + 0.01f);
        sfin[t + 256] = sqrtf(cs1 * (1.f / 4096.f) + 0.01f);
    }

    // EXT: BCE-with-logits for pairs t, t+256 (weight 0.01)
    {
        const float l0 = exist[t], l1 = exist[t + 256];
        const float gt0 = (cs0 > 24.f) ? 1.f : 0.f;
        const float gt1 = (cs1 > 24.f) ? 1.f : 0.f;
        const float e0v = fmaxf(l0, 0.f) - l0 * gt0 + log1pf(expf(-fabsf(l0)));
        const float e1v = fmaxf(l1, 0.f) - l1 * gt1 + log1pf(expf(-fabsf(l1)));
        acc += (e0v + e1v) * (0.01f / 512.f);
    }

    // CST: 512 (b,k) pairs, 2 per thread (weight 0.1)
    {
        const int p0i = t * 3, p1i = (t + 256) * 3;
        float dx0 = pam[p0i]     - trans[p0i];
        float dy0 = pam[p0i + 1] - trans[p0i + 1];
        float dz0 = pam[p0i + 2] - trans[p0i + 2];
        float dx1 = pam[p1i]     - trans[p1i];
        float dy1 = pam[p1i + 1] - trans[p1i + 1];
        float dz1 = pam[p1i + 2] - trans[p1i + 2];
        acc += (sqrtf(dx0 * dx0 + dy0 * dy0 + dz0 * dz0) +
                sqrtf(dx1 * dx1 + dy1 * dy1 + dz1 * dz1)) * (0.1f / 512.f);
    }

    // SPS: per-b mean over k of sfin, squared (weight 0.1)
    __syncthreads();
    if (t < 32) {
        float m = 0.f;
        #pragma unroll
        for (int kk2 = 0; kk2 < 16; kk2++) m += sfin[t * 16 + kk2];
        m *= (1.f / 16.f);
        acc += m * m * (0.1f / 32.f);
    }

    // block reduction of acc
    #pragma unroll
    for (int off = 16; off; off >>= 1)
        acc += __shfl_down_sync(0xffffffffu, acc, off);
    __syncthreads();
    if (lane == 0) srec[warp] = acc;
    __syncthreads();
    if (t == 0) {
        float s = 0.f;
        #pragma unroll
        for (int w = 0; w < 8; w++) s += srec[w];
        out[0] = s;
        g_count = 0;   // reset for next graph replay
    }
}

extern "C" void kernel_launch(void* const* d_in, const int* in_sizes, int n_in,
                              void* d_out, int out_size)
{
    const float* pc      = (const float*)d_in[0];
    const float* normals = (const float*)d_in[1];
    const float* randn   = (const float*)d_in[2];
    const float* scale   = (const float*)d_in[3];
    const float* shapes  = (const float*)d_in[4];
    const float* rotate  = (const float*)d_in[5];
    const float* pam     = (const float*)d_in[6];
    const float* assign  = (const float*)d_in[7];
    const float* exist   = (const float*)d_in[8];
    const float* mu      = (const float*)d_in[9];
    const float* logvar  = (const float*)d_in[10];
    const float* trans   = (const float*)d_in[11];
    float* out = (float*)d_out;

    loss_fused_kernel<<<GRIDA, 256>>>(pc, normals, randn, scale, shapes, rotate,
                                      pam, assign, exist, mu, logvar, trans, out);
}